// round 2
// baseline (speedup 1.0000x reference)
#include <cuda_runtime.h>

#define NN 50000
#define NE 800000
#define C 64
#define CIN 16
#define NL 4
#define HSTEP 0.1f
#define EPSV 1e-3f

// ---- static device scratch (no allocs allowed) ----
__device__ __align__(256) float g_Xn[NN * C];          // 12.8 MB
__device__ __align__(256) float g_Xe[(size_t)NE * C];  // 204.8 MB
__device__ __align__(256) float g_Z[NN * C];
__device__ __align__(256) float g_W[NN * C];
__device__ __align__(256) float g_U[NN * C];
__device__ __align__(256) float g_div[NN * C];
__device__ __align__(256) float g_scr[6 * C];  // sA qA sW qW sU qU
__device__ __align__(256) float g_nrm[6 * C];  // mA rA mW rW mU rU

__device__ __forceinline__ void red4(float* p, float x, float y, float z, float w) {
    asm volatile("red.global.add.v4.f32 [%0], {%1,%2,%3,%4};"
                 :: "l"(p), "f"(x), "f"(y), "f"(z), "f"(w) : "memory");
}

// zero div + scratch
__global__ void k_zero() {
    int stride = gridDim.x * blockDim.x;
    int t0 = blockIdx.x * blockDim.x + threadIdx.x;
    for (int i = t0; i < NN * C; i += stride) g_div[i] = 0.f;
    if (t0 < 6 * C) g_scr[t0] = 0.f;
}

// out[item][k] = sum_c K[k*CIN+c] * in[c*count+item]   (K is [C x CIN])
__global__ void k_open(const float* __restrict__ in, const float* __restrict__ K,
                       float* __restrict__ out, int count) {
    __shared__ __align__(16) float KT[CIN * C];  // KT[c*C + k]
    for (int idx = threadIdx.x; idx < CIN * C; idx += blockDim.x) {
        int k = idx & (C - 1); int c = idx >> 6;
        KT[idx] = K[k * CIN + c];
    }
    __syncthreads();
    int n = blockIdx.x * blockDim.x + threadIdx.x;
    if (n >= count) return;
    float4 acc[C / 4];
#pragma unroll
    for (int q = 0; q < C / 4; q++) acc[q] = make_float4(0.f, 0.f, 0.f, 0.f);
#pragma unroll
    for (int c = 0; c < CIN; c++) {
        float v = __ldg(&in[(size_t)c * count + n]);
        const float4* w = (const float4*)&KT[c * C];
#pragma unroll
        for (int q = 0; q < C / 4; q++) {
            float4 t = w[q];
            acc[q].x += t.x * v; acc[q].y += t.y * v;
            acc[q].z += t.z * v; acc[q].w += t.w * v;
        }
    }
    float4* o = (float4*)&out[(size_t)n * C];
#pragma unroll
    for (int q = 0; q < C / 4; q++) o[q] = acc[q];
}

__device__ __forceinline__ void fma_row(float4* acc, const float* MT, int c, float v) {
    const float4* w = (const float4*)&MT[c * C];
#pragma unroll
    for (int q = 0; q < 16; q++) {
        float4 t = w[q];
        acc[q].x += t.x * v; acc[q].y += t.y * v;
        acc[q].z += t.z * v; acc[q].w += t.w * v;
    }
}

// Out[n][k] = sum_c M[k*C+c] * In[n][c]   (64x64 weight)
__global__ void k_mm(const float* __restrict__ In, const float* __restrict__ M,
                     float* __restrict__ Out, int count) {
    __shared__ __align__(16) float MT[C * C];  // MT[c*C + k]
    for (int idx = threadIdx.x; idx < C * C; idx += blockDim.x) {
        int k = idx & (C - 1); int c = idx >> 6;
        MT[idx] = M[k * C + c];
    }
    __syncthreads();
    int n = blockIdx.x * blockDim.x + threadIdx.x;
    if (n >= count) return;
    float4 acc[16];
#pragma unroll
    for (int q = 0; q < 16; q++) acc[q] = make_float4(0.f, 0.f, 0.f, 0.f);
#pragma unroll
    for (int c4 = 0; c4 < 16; c4++) {
        float4 v4 = __ldg((const float4*)&In[(size_t)n * C + c4 * 4]);
        fma_row(acc, MT, c4 * 4 + 0, v4.x);
        fma_row(acc, MT, c4 * 4 + 1, v4.y);
        fma_row(acc, MT, c4 * 4 + 2, v4.z);
        fma_row(acc, MT, c4 * 4 + 3, v4.w);
    }
    float4* o = (float4*)&Out[(size_t)n * C];
#pragma unroll
    for (int q = 0; q < 16; q++) o[q] = acc[q];
}

// per-channel sum & sumsq of X[count][64] into g_scr[off .. off+127]
__global__ void k_stats(const float* __restrict__ X, int count, int off) {
    int t = blockIdx.x * blockDim.x + threadIdx.x;
    int c = t & (C - 1);
    int row0 = t >> 6;
    int nrows = (gridDim.x * blockDim.x) >> 6;
    float s = 0.f, q = 0.f;
    for (int n = row0; n < count; n += nrows) {
        float v = __ldg(&X[(size_t)n * C + c]);
        s += v; q += v * v;
    }
    __shared__ float ss[C], sq[C];
    if (threadIdx.x < C) { ss[threadIdx.x] = 0.f; sq[threadIdx.x] = 0.f; }
    __syncthreads();
    atomicAdd(&ss[c], s);
    atomicAdd(&sq[c], q);
    __syncthreads();
    if (threadIdx.x < C) {
        atomicAdd(&g_scr[off + threadIdx.x], ss[threadIdx.x]);
        atomicAdd(&g_scr[off + C + threadIdx.x], sq[threadIdx.x]);
    }
}

// edge sweep A: per-channel sum/sumsq of y = Z[:,i]-Z[:,j]  (16 lanes per edge)
__global__ void k_edgeA(const int* __restrict__ iInd, const int* __restrict__ jInd) {
    int t = blockIdx.x * blockDim.x + threadIdx.x;
    int lane = t & 15;
    int grp = t >> 4;
    int ngrp = (gridDim.x * blockDim.x) >> 4;
    float4 s = make_float4(0.f, 0.f, 0.f, 0.f);
    float4 q = make_float4(0.f, 0.f, 0.f, 0.f);
    for (int e = grp; e < NE; e += ngrp) {
        int i = __ldg(&iInd[e]);
        int j = __ldg(&jInd[e]);
        float4 a = __ldg((const float4*)&g_Z[(size_t)i * C + lane * 4]);
        float4 b = __ldg((const float4*)&g_Z[(size_t)j * C + lane * 4]);
        float yx = a.x - b.x, yy = a.y - b.y, yz = a.z - b.z, yw = a.w - b.w;
        s.x += yx; s.y += yy; s.z += yz; s.w += yw;
        q.x += yx * yx; q.y += yy * yy; q.z += yz * yz; q.w += yw * yw;
    }
    __shared__ float ss[C], sq[C];
    if (threadIdx.x < C) { ss[threadIdx.x] = 0.f; sq[threadIdx.x] = 0.f; }
    __syncthreads();
    int ch = lane * 4;
    atomicAdd(&ss[ch + 0], s.x); atomicAdd(&ss[ch + 1], s.y);
    atomicAdd(&ss[ch + 2], s.z); atomicAdd(&ss[ch + 3], s.w);
    atomicAdd(&sq[ch + 0], q.x); atomicAdd(&sq[ch + 1], q.y);
    atomicAdd(&sq[ch + 2], q.z); atomicAdd(&sq[ch + 3], q.w);
    __syncthreads();
    if (threadIdx.x < C) {
        atomicAdd(&g_scr[threadIdx.x], ss[threadIdx.x]);
        atomicAdd(&g_scr[C + threadIdx.x], sq[threadIdx.x]);
    }
}

// compute mean / 1/sqrt(sumsq_centered + eps)
__global__ void k_scales(int which) {
    int c = threadIdx.x;
    if (c >= C) return;
    if (which == 0) {
        float s = g_scr[c], q = g_scr[C + c];
        float m = s / (float)NE;
        g_nrm[c] = m;
        g_nrm[C + c] = 1.f / sqrtf(fmaxf(q - s * m, 0.f) + EPSV);
        s = g_scr[2 * C + c]; q = g_scr[3 * C + c];
        m = s / (float)NN;
        g_nrm[2 * C + c] = m;
        g_nrm[3 * C + c] = 1.f / sqrtf(fmaxf(q - s * m, 0.f) + EPSV);
    } else {
        float s = g_scr[4 * C + c], q = g_scr[5 * C + c];
        float m = s / (float)NN;
        g_nrm[4 * C + c] = m;
        g_nrm[5 * C + c] = 1.f / sqrtf(fmaxf(q - s * m, 0.f) + EPSV);
    }
}

// edge sweep B: xe += H*relu((y-m)*r); scatter +/- xe into div
__global__ void k_edgeB(const int* __restrict__ iInd, const int* __restrict__ jInd) {
    __shared__ __align__(16) float sm[2 * C];
    if (threadIdx.x < C) {
        sm[threadIdx.x] = g_nrm[threadIdx.x];
        sm[C + threadIdx.x] = g_nrm[C + threadIdx.x];
    }
    __syncthreads();
    int t = blockIdx.x * blockDim.x + threadIdx.x;
    int e = t >> 4;
    if (e >= NE) return;
    int lane = t & 15;
    int i = __ldg(&iInd[e]);
    int j = __ldg(&jInd[e]);
    float4 a = __ldg((const float4*)&g_Z[(size_t)i * C + lane * 4]);
    float4 b = __ldg((const float4*)&g_Z[(size_t)j * C + lane * 4]);
    float4 m = *(const float4*)&sm[lane * 4];
    float4 r = *(const float4*)&sm[C + lane * 4];
    float4 xe = *(const float4*)&g_Xe[(size_t)e * C + lane * 4];
    xe.x += HSTEP * fmaxf((a.x - b.x - m.x) * r.x, 0.f);
    xe.y += HSTEP * fmaxf((a.y - b.y - m.y) * r.y, 0.f);
    xe.z += HSTEP * fmaxf((a.z - b.z - m.z) * r.z, 0.f);
    xe.w += HSTEP * fmaxf((a.w - b.w - m.w) * r.w, 0.f);
    *(float4*)&g_Xe[(size_t)e * C + lane * 4] = xe;
    red4(&g_div[(size_t)i * C + lane * 4], xe.x, xe.y, xe.z, xe.w);
    red4(&g_div[(size_t)j * C + lane * 4], -xe.x, -xe.y, -xe.z, -xe.w);
}

// xn -= H * (relu(norm(U)) + relu(norm(W)))
__global__ void k_update() {
    __shared__ __align__(16) float sm[4 * C];  // mW rW mU rU
    if (threadIdx.x < C) {
        sm[threadIdx.x]         = g_nrm[2 * C + threadIdx.x];
        sm[C + threadIdx.x]     = g_nrm[3 * C + threadIdx.x];
        sm[2 * C + threadIdx.x] = g_nrm[4 * C + threadIdx.x];
        sm[3 * C + threadIdx.x] = g_nrm[5 * C + threadIdx.x];
    }
    __syncthreads();
    int n = blockIdx.x * blockDim.x + threadIdx.x;
    if (n >= NN) return;
#pragma unroll
    for (int q = 0; q < 16; q++) {
        float4 u = *(const float4*)&g_U[(size_t)n * C + q * 4];
        float4 w = *(const float4*)&g_W[(size_t)n * C + q * 4];
        float4 x = *(float4*)&g_Xn[(size_t)n * C + q * 4];
        float4 mw = *(const float4*)&sm[q * 4];
        float4 rw = *(const float4*)&sm[C + q * 4];
        float4 mu = *(const float4*)&sm[2 * C + q * 4];
        float4 ru = *(const float4*)&sm[3 * C + q * 4];
        x.x -= HSTEP * (fmaxf((u.x - mu.x) * ru.x, 0.f) + fmaxf((w.x - mw.x) * rw.x, 0.f));
        x.y -= HSTEP * (fmaxf((u.y - mu.y) * ru.y, 0.f) + fmaxf((w.y - mw.y) * rw.y, 0.f));
        x.z -= HSTEP * (fmaxf((u.z - mu.z) * ru.z, 0.f) + fmaxf((w.z - mw.z) * rw.z, 0.f));
        x.w -= HSTEP * (fmaxf((u.w - mu.w) * ru.w, 0.f) + fmaxf((w.w - mw.w) * rw.w, 0.f));
        *(float4*)&g_Xn[(size_t)n * C + q * 4] = x;
    }
}

// out[co*count + n] = sum_k Kc[co*C+k] * In[n][k]   (Kc is [16 x 64])
__global__ void k_close(const float* __restrict__ Kc, const float* __restrict__ In,
                        float* __restrict__ out, int count) {
    __shared__ __align__(16) float Ks[CIN * C];
    for (int idx = threadIdx.x; idx < CIN * C; idx += blockDim.x) Ks[idx] = Kc[idx];
    __syncthreads();
    int n = blockIdx.x * blockDim.x + threadIdx.x;
    if (n >= count) return;
    float4 row[16];
#pragma unroll
    for (int q = 0; q < 16; q++)
        row[q] = __ldg((const float4*)&In[(size_t)n * C + q * 4]);
#pragma unroll
    for (int co = 0; co < CIN; co++) {
        float acc = 0.f;
#pragma unroll
        for (int q = 0; q < 16; q++) {
            float4 w = *(const float4*)&Ks[co * C + q * 4];
            acc += w.x * row[q].x + w.y * row[q].y + w.z * row[q].z + w.w * row[q].w;
        }
        out[(size_t)co * count + n] = acc;
    }
}

extern "C" void kernel_launch(void* const* d_in, const int* in_sizes, int n_in,
                              void* d_out, int out_size) {
    const float* xn      = (const float*)d_in[0];
    const float* xe      = (const float*)d_in[1];
    const int*   iInd    = (const int*)d_in[2];
    const int*   jInd    = (const int*)d_in[3];
    const float* KNopen  = (const float*)d_in[4];
    const float* KEopen  = (const float*)d_in[5];
    const float* KNclose = (const float*)d_in[6];
    const float* KEclose = (const float*)d_in[7];
    const float* KN      = (const float*)d_in[8];
    const float* KE      = (const float*)d_in[9];
    const float* KD      = (const float*)d_in[10];
    float* out = (float*)d_out;
    (void)in_sizes; (void)n_in; (void)out_size;

    float *pXn, *pXe, *pZ, *pW, *pU, *pDiv;
    cudaGetSymbolAddress((void**)&pXn, g_Xn);
    cudaGetSymbolAddress((void**)&pXe, g_Xe);
    cudaGetSymbolAddress((void**)&pZ, g_Z);
    cudaGetSymbolAddress((void**)&pW, g_W);
    cudaGetSymbolAddress((void**)&pU, g_U);
    cudaGetSymbolAddress((void**)&pDiv, g_div);

    const int TB = 256;
    const int gN = (NN + TB - 1) / TB;
    const int gE = (NE + TB - 1) / TB;
    const int gEB = ((NE * 16) + TB - 1) / TB;

    k_open<<<gN, TB>>>(xn, KNopen, pXn, NN);
    k_open<<<gE, TB>>>(xe, KEopen, pXe, NE);

    for (int l = 0; l < NL; l++) {
        const float* Kn = KN + (size_t)l * C * C;
        const float* Ke = KE + (size_t)l * C * C;
        const float* Kd = KD + (size_t)l * C * C;

        k_zero<<<256, TB>>>();
        k_mm<<<gN, TB>>>(pXn, Kn, pZ, NN);
        k_mm<<<gN, TB>>>(pXn, Kd, pW, NN);
        k_stats<<<256, TB>>>(pW, NN, 2 * C);
        k_edgeA<<<2048, TB>>>(iInd, jInd);
        k_scales<<<1, 64>>>(0);
        k_edgeB<<<gEB, TB>>>(iInd, jInd);
        k_mm<<<gN, TB>>>(pDiv, Ke, pU, NN);
        k_stats<<<256, TB>>>(pU, NN, 4 * C);
        k_scales<<<1, 64>>>(1);
        k_update<<<gN, TB>>>();
    }

    k_close<<<gN, TB>>>(KNclose, pXn, out, NN);
    k_close<<<gE, TB>>>(KEclose, pXe, out + (size_t)CIN * NN, NE);
}

// round 3
// speedup vs baseline: 1.0025x; 1.0025x over previous
#include <cuda_runtime.h>

#define NN 50000
#define NE 800000
#define C 64
#define CIN 16
#define NL 4
#define HSTEP 0.1f
#define EPSV 1e-3f

// ---- static device scratch (no allocs allowed) ----
__device__ __align__(256) float g_Xn[NN * C];          // 12.8 MB
__device__ __align__(256) float g_Xe[(size_t)NE * C];  // 204.8 MB
__device__ __align__(256) float g_Z[NN * C];
__device__ __align__(256) float g_W[NN * C];
__device__ __align__(256) float g_U[NN * C];
__device__ __align__(256) float g_div[NN * C];
__device__ __align__(256) float g_scr[6 * C];  // sA qA sW qW sU qU
__device__ __align__(256) float g_nrm[6 * C];  // mA rA mW rW mU rU

__device__ __forceinline__ void red4(float* p, float x, float y, float z, float w) {
    asm volatile("red.global.add.v4.f32 [%0], {%1,%2,%3,%4};"
                 :: "l"(p), "f"(x), "f"(y), "f"(z), "f"(w) : "memory");
}

// zero div + scratch
__global__ void k_zero() {
    int stride = gridDim.x * blockDim.x;
    int t0 = blockIdx.x * blockDim.x + threadIdx.x;
    for (int i = t0; i < NN * C; i += stride) g_div[i] = 0.f;
    if (t0 < 6 * C) g_scr[t0] = 0.f;
}

// out[item][k] = sum_c K[k*CIN+c] * in[c*count+item]   (K is [C x CIN])
__global__ void k_open(const float* __restrict__ in, const float* __restrict__ K,
                       float* __restrict__ out, int count) {
    __shared__ __align__(16) float KT[CIN * C];  // KT[c*C + k]
    for (int idx = threadIdx.x; idx < CIN * C; idx += blockDim.x) {
        int k = idx & (C - 1); int c = idx >> 6;
        KT[idx] = K[k * CIN + c];
    }
    __syncthreads();
    int n = blockIdx.x * blockDim.x + threadIdx.x;
    if (n >= count) return;
    float4 acc[C / 4];
#pragma unroll
    for (int q = 0; q < C / 4; q++) acc[q] = make_float4(0.f, 0.f, 0.f, 0.f);
#pragma unroll
    for (int c = 0; c < CIN; c++) {
        float v = __ldg(&in[(size_t)c * count + n]);
        const float4* w = (const float4*)&KT[c * C];
#pragma unroll
        for (int q = 0; q < C / 4; q++) {
            float4 t = w[q];
            acc[q].x += t.x * v; acc[q].y += t.y * v;
            acc[q].z += t.z * v; acc[q].w += t.w * v;
        }
    }
    float4* o = (float4*)&out[(size_t)n * C];
#pragma unroll
    for (int q = 0; q < C / 4; q++) o[q] = acc[q];
}

__device__ __forceinline__ void fma_row(float4* acc, const float* MT, int c, float v) {
    const float4* w = (const float4*)&MT[c * C];
#pragma unroll
    for (int q = 0; q < 16; q++) {
        float4 t = w[q];
        acc[q].x += t.x * v; acc[q].y += t.y * v;
        acc[q].z += t.z * v; acc[q].w += t.w * v;
    }
}

// Out[n][k] = sum_c M[k*C+c] * In[n][c]   (64x64 weight)
__global__ void k_mm(const float* __restrict__ In, const float* __restrict__ M,
                     float* __restrict__ Out, int count) {
    __shared__ __align__(16) float MT[C * C];  // MT[c*C + k]
    for (int idx = threadIdx.x; idx < C * C; idx += blockDim.x) {
        int k = idx & (C - 1); int c = idx >> 6;
        MT[idx] = M[k * C + c];
    }
    __syncthreads();
    int n = blockIdx.x * blockDim.x + threadIdx.x;
    if (n >= count) return;
    float4 acc[16];
#pragma unroll
    for (int q = 0; q < 16; q++) acc[q] = make_float4(0.f, 0.f, 0.f, 0.f);
#pragma unroll
    for (int c4 = 0; c4 < 16; c4++) {
        float4 v4 = __ldg((const float4*)&In[(size_t)n * C + c4 * 4]);
        fma_row(acc, MT, c4 * 4 + 0, v4.x);
        fma_row(acc, MT, c4 * 4 + 1, v4.y);
        fma_row(acc, MT, c4 * 4 + 2, v4.z);
        fma_row(acc, MT, c4 * 4 + 3, v4.w);
    }
    float4* o = (float4*)&Out[(size_t)n * C];
#pragma unroll
    for (int q = 0; q < 16; q++) o[q] = acc[q];
}

// per-channel sum & sumsq of X[count][64] into g_scr[off .. off+127]
__global__ void k_stats(const float* __restrict__ X, int count, int off) {
    int t = blockIdx.x * blockDim.x + threadIdx.x;
    int c = t & (C - 1);
    int row0 = t >> 6;
    int nrows = (gridDim.x * blockDim.x) >> 6;
    float s = 0.f, q = 0.f;
    for (int n = row0; n < count; n += nrows) {
        float v = __ldg(&X[(size_t)n * C + c]);
        s += v; q += v * v;
    }
    __shared__ float ss[C], sq[C];
    if (threadIdx.x < C) { ss[threadIdx.x] = 0.f; sq[threadIdx.x] = 0.f; }
    __syncthreads();
    atomicAdd(&ss[c], s);
    atomicAdd(&sq[c], q);
    __syncthreads();
    if (threadIdx.x < C) {
        atomicAdd(&g_scr[off + threadIdx.x], ss[threadIdx.x]);
        atomicAdd(&g_scr[off + C + threadIdx.x], sq[threadIdx.x]);
    }
}

// edge sweep A: per-channel sum/sumsq of y = Z[:,i]-Z[:,j]  (16 lanes per edge)
__global__ void k_edgeA(const int* __restrict__ iInd, const int* __restrict__ jInd) {
    int t = blockIdx.x * blockDim.x + threadIdx.x;
    int lane = t & 15;
    int grp = t >> 4;
    int ngrp = (gridDim.x * blockDim.x) >> 4;
    float4 s = make_float4(0.f, 0.f, 0.f, 0.f);
    float4 q = make_float4(0.f, 0.f, 0.f, 0.f);
    for (int e = grp; e < NE; e += ngrp) {
        int i = __ldg(&iInd[e]);
        int j = __ldg(&jInd[e]);
        float4 a = __ldg((const float4*)&g_Z[(size_t)i * C + lane * 4]);
        float4 b = __ldg((const float4*)&g_Z[(size_t)j * C + lane * 4]);
        float yx = a.x - b.x, yy = a.y - b.y, yz = a.z - b.z, yw = a.w - b.w;
        s.x += yx; s.y += yy; s.z += yz; s.w += yw;
        q.x += yx * yx; q.y += yy * yy; q.z += yz * yz; q.w += yw * yw;
    }
    __shared__ float ss[C], sq[C];
    if (threadIdx.x < C) { ss[threadIdx.x] = 0.f; sq[threadIdx.x] = 0.f; }
    __syncthreads();
    int ch = lane * 4;
    atomicAdd(&ss[ch + 0], s.x); atomicAdd(&ss[ch + 1], s.y);
    atomicAdd(&ss[ch + 2], s.z); atomicAdd(&ss[ch + 3], s.w);
    atomicAdd(&sq[ch + 0], q.x); atomicAdd(&sq[ch + 1], q.y);
    atomicAdd(&sq[ch + 2], q.z); atomicAdd(&sq[ch + 3], q.w);
    __syncthreads();
    if (threadIdx.x < C) {
        atomicAdd(&g_scr[threadIdx.x], ss[threadIdx.x]);
        atomicAdd(&g_scr[C + threadIdx.x], sq[threadIdx.x]);
    }
}

// compute mean / 1/sqrt(sumsq_centered + eps)
__global__ void k_scales(int which) {
    int c = threadIdx.x;
    if (c >= C) return;
    if (which == 0) {
        float s = g_scr[c], q = g_scr[C + c];
        float m = s / (float)NE;
        g_nrm[c] = m;
        g_nrm[C + c] = 1.f / sqrtf(fmaxf(q - s * m, 0.f) + EPSV);
        s = g_scr[2 * C + c]; q = g_scr[3 * C + c];
        m = s / (float)NN;
        g_nrm[2 * C + c] = m;
        g_nrm[3 * C + c] = 1.f / sqrtf(fmaxf(q - s * m, 0.f) + EPSV);
    } else {
        float s = g_scr[4 * C + c], q = g_scr[5 * C + c];
        float m = s / (float)NN;
        g_nrm[4 * C + c] = m;
        g_nrm[5 * C + c] = 1.f / sqrtf(fmaxf(q - s * m, 0.f) + EPSV);
    }
}

// edge sweep B: xe += H*relu((y-m)*r); scatter +/- xe into div
__global__ void k_edgeB(const int* __restrict__ iInd, const int* __restrict__ jInd) {
    __shared__ __align__(16) float sm[2 * C];
    if (threadIdx.x < C) {
        sm[threadIdx.x] = g_nrm[threadIdx.x];
        sm[C + threadIdx.x] = g_nrm[C + threadIdx.x];
    }
    __syncthreads();
    int t = blockIdx.x * blockDim.x + threadIdx.x;
    int e = t >> 4;
    if (e >= NE) return;
    int lane = t & 15;
    int i = __ldg(&iInd[e]);
    int j = __ldg(&jInd[e]);
    float4 a = __ldg((const float4*)&g_Z[(size_t)i * C + lane * 4]);
    float4 b = __ldg((const float4*)&g_Z[(size_t)j * C + lane * 4]);
    float4 m = *(const float4*)&sm[lane * 4];
    float4 r = *(const float4*)&sm[C + lane * 4];
    float4 xe = *(const float4*)&g_Xe[(size_t)e * C + lane * 4];
    xe.x += HSTEP * fmaxf((a.x - b.x - m.x) * r.x, 0.f);
    xe.y += HSTEP * fmaxf((a.y - b.y - m.y) * r.y, 0.f);
    xe.z += HSTEP * fmaxf((a.z - b.z - m.z) * r.z, 0.f);
    xe.w += HSTEP * fmaxf((a.w - b.w - m.w) * r.w, 0.f);
    *(float4*)&g_Xe[(size_t)e * C + lane * 4] = xe;
    red4(&g_div[(size_t)i * C + lane * 4], xe.x, xe.y, xe.z, xe.w);
    red4(&g_div[(size_t)j * C + lane * 4], -xe.x, -xe.y, -xe.z, -xe.w);
}

// xn -= H * (relu(norm(U)) + relu(norm(W)))
__global__ void k_update() {
    __shared__ __align__(16) float sm[4 * C];  // mW rW mU rU
    if (threadIdx.x < C) {
        sm[threadIdx.x]         = g_nrm[2 * C + threadIdx.x];
        sm[C + threadIdx.x]     = g_nrm[3 * C + threadIdx.x];
        sm[2 * C + threadIdx.x] = g_nrm[4 * C + threadIdx.x];
        sm[3 * C + threadIdx.x] = g_nrm[5 * C + threadIdx.x];
    }
    __syncthreads();
    int n = blockIdx.x * blockDim.x + threadIdx.x;
    if (n >= NN) return;
#pragma unroll
    for (int q = 0; q < 16; q++) {
        float4 u = *(const float4*)&g_U[(size_t)n * C + q * 4];
        float4 w = *(const float4*)&g_W[(size_t)n * C + q * 4];
        float4 x = *(float4*)&g_Xn[(size_t)n * C + q * 4];
        float4 mw = *(const float4*)&sm[q * 4];
        float4 rw = *(const float4*)&sm[C + q * 4];
        float4 mu = *(const float4*)&sm[2 * C + q * 4];
        float4 ru = *(const float4*)&sm[3 * C + q * 4];
        x.x -= HSTEP * (fmaxf((u.x - mu.x) * ru.x, 0.f) + fmaxf((w.x - mw.x) * rw.x, 0.f));
        x.y -= HSTEP * (fmaxf((u.y - mu.y) * ru.y, 0.f) + fmaxf((w.y - mw.y) * rw.y, 0.f));
        x.z -= HSTEP * (fmaxf((u.z - mu.z) * ru.z, 0.f) + fmaxf((w.z - mw.z) * rw.z, 0.f));
        x.w -= HSTEP * (fmaxf((u.w - mu.w) * ru.w, 0.f) + fmaxf((w.w - mw.w) * rw.w, 0.f));
        *(float4*)&g_Xn[(size_t)n * C + q * 4] = x;
    }
}

// out[co*count + n] = sum_k Kc[co*C+k] * In[n][k]   (Kc is [16 x 64])
__global__ void k_close(const float* __restrict__ Kc, const float* __restrict__ In,
                        float* __restrict__ out, int count) {
    __shared__ __align__(16) float Ks[CIN * C];
    for (int idx = threadIdx.x; idx < CIN * C; idx += blockDim.x) Ks[idx] = Kc[idx];
    __syncthreads();
    int n = blockIdx.x * blockDim.x + threadIdx.x;
    if (n >= count) return;
    float4 row[16];
#pragma unroll
    for (int q = 0; q < 16; q++)
        row[q] = __ldg((const float4*)&In[(size_t)n * C + q * 4]);
#pragma unroll
    for (int co = 0; co < CIN; co++) {
        float acc = 0.f;
#pragma unroll
        for (int q = 0; q < 16; q++) {
            float4 w = *(const float4*)&Ks[co * C + q * 4];
            acc += w.x * row[q].x + w.y * row[q].y + w.z * row[q].z + w.w * row[q].w;
        }
        out[(size_t)co * count + n] = acc;
    }
}

extern "C" void kernel_launch(void* const* d_in, const int* in_sizes, int n_in,
                              void* d_out, int out_size) {
    const float* xn      = (const float*)d_in[0];
    const float* xe      = (const float*)d_in[1];
    const int*   iInd    = (const int*)d_in[2];
    const int*   jInd    = (const int*)d_in[3];
    const float* KNopen  = (const float*)d_in[4];
    const float* KEopen  = (const float*)d_in[5];
    const float* KNclose = (const float*)d_in[6];
    const float* KEclose = (const float*)d_in[7];
    const float* KN      = (const float*)d_in[8];
    const float* KE      = (const float*)d_in[9];
    const float* KD      = (const float*)d_in[10];
    float* out = (float*)d_out;
    (void)in_sizes; (void)n_in; (void)out_size;

    float *pXn, *pXe, *pZ, *pW, *pU, *pDiv;
    cudaGetSymbolAddress((void**)&pXn, g_Xn);
    cudaGetSymbolAddress((void**)&pXe, g_Xe);
    cudaGetSymbolAddress((void**)&pZ, g_Z);
    cudaGetSymbolAddress((void**)&pW, g_W);
    cudaGetSymbolAddress((void**)&pU, g_U);
    cudaGetSymbolAddress((void**)&pDiv, g_div);

    const int TB = 256;
    const int gN = (NN + TB - 1) / TB;
    const int gE = (NE + TB - 1) / TB;
    const int gEB = ((NE * 16) + TB - 1) / TB;

    k_open<<<gN, TB>>>(xn, KNopen, pXn, NN);
    k_open<<<gE, TB>>>(xe, KEopen, pXe, NE);

    for (int l = 0; l < NL; l++) {
        const float* Kn = KN + (size_t)l * C * C;
        const float* Ke = KE + (size_t)l * C * C;
        const float* Kd = KD + (size_t)l * C * C;

        k_zero<<<256, TB>>>();
        k_mm<<<gN, TB>>>(pXn, Kn, pZ, NN);
        k_mm<<<gN, TB>>>(pXn, Kd, pW, NN);
        k_stats<<<256, TB>>>(pW, NN, 2 * C);
        k_edgeA<<<2048, TB>>>(iInd, jInd);
        k_scales<<<1, 64>>>(0);
        k_edgeB<<<gEB, TB>>>(iInd, jInd);
        k_mm<<<gN, TB>>>(pDiv, Ke, pU, NN);
        k_stats<<<256, TB>>>(pU, NN, 4 * C);
        k_scales<<<1, 64>>>(1);
        k_update<<<gN, TB>>>();
    }

    k_close<<<gN, TB>>>(KNclose, pXn, out, NN);
    k_close<<<gE, TB>>>(KEclose, pXe, out + (size_t)CIN * NN, NE);
}